// round 4
// baseline (speedup 1.0000x reference)
#include <cuda_runtime.h>
#include <cstdint>
#include <math.h>

#define B   64
#define T   512
#define E   512
#define H   1024
#define G4  4096
#define NC  32000
#define VOCABM1 31999
#define GRID_REC 128   // CTAs in persistent recurrence (1/SM, all co-resident)

// ---------------- scratch (device globals: allocation-free rule) ----------------
__device__ __align__(16) float g_x0[(size_t)B * T * E];    // embedded input [B*T][E]
__device__ __align__(16) float g_xg[(size_t)B * T * G4];   // input projections [B*T][4H]
__device__ __align__(16) float g_h1[(size_t)B * T * H];    // layer-0 h, [B][T][H] (for L1 proj)
__device__ __align__(16) float g_hT[(size_t)T * H * B];    // h in [t][k][b] (recurrence feed)
__device__ __align__(16) float g_last[(size_t)B * H];      // h2 gathered at seq_lens
__device__ int g_seqlen[B];
__device__ unsigned g_bar_count;
__device__ unsigned g_bar_gen;

// ---------------- small helpers: packed f32x2 ----------------
__device__ __forceinline__ void ffma2(unsigned long long& d, unsigned long long a,
                                      unsigned long long b2) {
    asm("fma.rn.f32x2 %0, %1, %2, %0;" : "+l"(d) : "l"(a), "l"(b2));
}
__device__ __forceinline__ unsigned long long pk2(float lo, float hi) {
    unsigned long long r;
    asm("mov.b64 %0, {%1, %2};" : "=l"(r) : "f"(lo), "f"(hi));
    return r;
}
__device__ __forceinline__ float2 upk(unsigned long long v) {
    float2 f;
    asm("mov.b64 {%0, %1}, %2;" : "=f"(f.x), "=f"(f.y) : "l"(v));
    return f;
}
__device__ __forceinline__ float sigm(float x) { return 1.f / (1.f + expf(-x)); }

// ---------------- seq_lens ----------------
__global__ void seqlen_kernel(const int* __restrict__ feat, int* __restrict__ out) {
    int b = blockIdx.x;
    int tid = threadIdx.x;
    int cnt = 0;
    for (int t = tid; t < T; t += blockDim.x)
        cnt += (feat[b * T + t] != VOCABM1) ? 1 : 0;
    __shared__ int s[256];
    s[tid] = cnt;
    __syncthreads();
    for (int o = 128; o > 0; o >>= 1) {
        if (tid < o) s[tid] += s[tid + o];
        __syncthreads();
    }
    if (tid == 0) out[b] = s[0] - 1;
}

// ---------------- embedding gather ----------------
__global__ void embed_kernel(const int* __restrict__ feat,
                             const float* __restrict__ emb,
                             float* __restrict__ x0) {
    int bt = blockIdx.x;
    int f = feat[bt];
    const float4* s = (const float4*)(emb + (size_t)f * E);
    float4* d = (float4*)(x0 + (size_t)bt * E);
    d[threadIdx.x] = s[threadIdx.x];
}

// ---------------- TN GEMM: C[m][n] = sum_k A[m][k]*W[n][k] (+ b1[n] + b2[n]) ----
__global__ void gemm_tn(const float* __restrict__ A, long lda,
                        const float* __restrict__ W, int ldw,
                        const float* __restrict__ b1, const float* __restrict__ b2,
                        float* __restrict__ C, int ldc, int K) {
    __shared__ float As[16][68];
    __shared__ float Bs[16][68];

    const int tid = threadIdx.x;
    const int m0 = blockIdx.y * 64;
    const int n0 = blockIdx.x * 64;

    const float* Ap = A + (long)m0 * lda;
    const float* Wp = W + (long)n0 * ldw;

    const int lr = tid >> 2;
    const int lk = (tid & 3) * 4;
    const int ty = tid >> 4;
    const int tx = tid & 15;

    float acc[4][4];
#pragma unroll
    for (int i = 0; i < 4; i++)
#pragma unroll
        for (int j = 0; j < 4; j++) acc[i][j] = 0.f;

    for (int kt = 0; kt < K; kt += 16) {
        float4 a4 = *(const float4*)(Ap + (long)lr * lda + kt + lk);
        float4 w4 = *(const float4*)(Wp + (long)lr * ldw + kt + lk);
        As[lk + 0][lr] = a4.x; As[lk + 1][lr] = a4.y;
        As[lk + 2][lr] = a4.z; As[lk + 3][lr] = a4.w;
        Bs[lk + 0][lr] = w4.x; Bs[lk + 1][lr] = w4.y;
        Bs[lk + 2][lr] = w4.z; Bs[lk + 3][lr] = w4.w;
        __syncthreads();
#pragma unroll
        for (int kk = 0; kk < 16; kk++) {
            float4 a = *(const float4*)&As[kk][ty * 4];
            float4 b = *(const float4*)&Bs[kk][tx * 4];
            acc[0][0] += a.x * b.x; acc[0][1] += a.x * b.y;
            acc[0][2] += a.x * b.z; acc[0][3] += a.x * b.w;
            acc[1][0] += a.y * b.x; acc[1][1] += a.y * b.y;
            acc[1][2] += a.y * b.z; acc[1][3] += a.y * b.w;
            acc[2][0] += a.z * b.x; acc[2][1] += a.z * b.y;
            acc[2][2] += a.z * b.z; acc[2][3] += a.z * b.w;
            acc[3][0] += a.w * b.x; acc[3][1] += a.w * b.y;
            acc[3][2] += a.w * b.z; acc[3][3] += a.w * b.w;
        }
        __syncthreads();
    }

#pragma unroll
    for (int i = 0; i < 4; i++) {
        int m = m0 + ty * 4 + i;
#pragma unroll
        for (int j = 0; j < 4; j++) {
            int n = n0 + tx * 4 + j;
            float v = acc[i][j];
            if (b1) v += b1[n];
            if (b2) v += b2[n];
            C[(long)m * ldc + n] = v;
        }
    }
}

// ---------------- persistent LSTM recurrence ----------------
// 128 CTAs; CTA c owns hidden units [8c, 8c+8) = 32 gate rows of w_hh, kept in SMEM.
// Per step: gates = xg_t + h_{t-1} @ w_hh^T (f32x2 FFMA), cell elementwise (c in regs),
// h written to hT[t][k][b] (and [B][T][H] copy for layer 0), then grid barrier.
extern __shared__ float smem[];

__global__ void __launch_bounds__(256, 1)
lstm_rec(const float* __restrict__ xg, const float* __restrict__ w_hh,
         float* __restrict__ hT, float* __restrict__ h1,
         const int* __restrict__ seqlen, float* __restrict__ last) {
    float* ws = smem;                      // [16 pairs][1024 k] float2 = 32768 floats
    float* hb0 = smem + 32768;             // h chunk buf A: [128 k][64 b]
    float* hb1 = smem + 40960;             // h chunk buf B

    const int tid = threadIdx.x;
    const int cta = blockIdx.x;
    const int kblk = cta * 8;
    const int b = tid & 63;
    const int q = tid >> 6;                // 0..3 -> hidden pair (2q, 2q+1)

    // ---- load weight slice into SMEM, f32x2 pair-interleaved ----
    // pair p = g*4 + q covers rows n = g*1024 + kblk + {2q, 2q+1}
    for (int j = 0; j < 32; j++) {
        int n = ((j >> 3) << 10) + kblk + (j & 7);
        const float* src = w_hh + (size_t)n * H;
        float* dst = ws + (size_t)(j >> 1) * 2048 + (j & 1);
        for (int k = tid; k < H; k += 256) dst[k * 2] = src[k];
    }
    __syncthreads();

    const int myseq = seqlen[b];
    float c_0 = 0.f, c_1 = 0.f;
    const size_t xg_b = (size_t)b * T * G4;
    const int k0 = kblk + 2 * q;

    for (int t = 0; t < T; t++) {
        // xg preactivation pairs (issued early, consumed at acc init)
        const float* xr = xg + xg_b + (size_t)t * G4 + k0;
        float2 x_i = *(const float2*)(xr);
        float2 x_f = *(const float2*)(xr + H);
        float2 x_g = *(const float2*)(xr + 2 * H);
        float2 x_o = *(const float2*)(xr + 3 * H);

        unsigned long long acc0 = pk2(x_i.x, x_i.y);
        unsigned long long acc1 = pk2(x_f.x, x_f.y);
        unsigned long long acc2 = pk2(x_g.x, x_g.y);
        unsigned long long acc3 = pk2(x_o.x, x_o.y);

        if (t > 0) {
            const float* hsrc = hT + (size_t)(t - 1) * H * B;   // [k][b]
            float4 r[8];
            // preload chunk 0 (32KB = 2048 float4)
#pragma unroll
            for (int i = 0; i < 8; i++)
                r[i] = ((const float4*)hsrc)[tid + i * 256];
#pragma unroll
            for (int i = 0; i < 8; i++)
                ((float4*)hb0)[tid + i * 256] = r[i];
            __syncthreads();

            for (int ch = 0; ch < 8; ch++) {
                if (ch < 7) {
                    const float4* s = (const float4*)(hsrc + (size_t)(ch + 1) * 128 * B);
#pragma unroll
                    for (int i = 0; i < 8; i++) r[i] = s[tid + i * 256];
                }
                const float* hs = (ch & 1) ? hb1 : hb0;
                const int kg = ch * 128;
                // ws as float2: pair p at float2 index p*1024 + k
                const float* w0 = ws + (size_t)((0 * 4 + q) * 1024 + kg) * 2;
                const float* w1 = ws + (size_t)((1 * 4 + q) * 1024 + kg) * 2;
                const float* w2 = ws + (size_t)((2 * 4 + q) * 1024 + kg) * 2;
                const float* w3 = ws + (size_t)((3 * 4 + q) * 1024 + kg) * 2;
#pragma unroll 8
                for (int kk = 0; kk < 128; kk += 2) {
                    float hv0 = hs[kk * 64 + b];
                    float hv1 = hs[(kk + 1) * 64 + b];
                    unsigned long long hh0 = pk2(hv0, hv0);
                    unsigned long long hh1 = pk2(hv1, hv1);
                    float4 wv;
                    wv = *(const float4*)(w0 + kk * 2);
                    ffma2(acc0, hh0, pk2(wv.x, wv.y));
                    ffma2(acc0, hh1, pk2(wv.z, wv.w));
                    wv = *(const float4*)(w1 + kk * 2);
                    ffma2(acc1, hh0, pk2(wv.x, wv.y));
                    ffma2(acc1, hh1, pk2(wv.z, wv.w));
                    wv = *(const float4*)(w2 + kk * 2);
                    ffma2(acc2, hh0, pk2(wv.x, wv.y));
                    ffma2(acc2, hh1, pk2(wv.z, wv.w));
                    wv = *(const float4*)(w3 + kk * 2);
                    ffma2(acc3, hh0, pk2(wv.x, wv.y));
                    ffma2(acc3, hh1, pk2(wv.z, wv.w));
                }
                if (ch < 7) {
                    float* dst = (ch & 1) ? hb0 : hb1;
#pragma unroll
                    for (int i = 0; i < 8; i++)
                        ((float4*)dst)[tid + i * 256] = r[i];
                    __syncthreads();
                }
            }
        }

        // ---- cell (two hidden units per thread, c kept in registers) ----
        float2 pi = upk(acc0), pf = upk(acc1), pg = upk(acc2), po = upk(acc3);
        float i0 = sigm(pi.x), f0 = sigm(pf.x), g0 = tanhf(pg.x), o0 = sigm(po.x);
        float i1 = sigm(pi.y), f1 = sigm(pf.y), g1 = tanhf(pg.y), o1 = sigm(po.y);
        c_0 = f0 * c_0 + i0 * g0;
        c_1 = f1 * c_1 + i1 * g1;
        float h_0 = o0 * tanhf(c_0);
        float h_1 = o1 * tanhf(c_1);

        hT[((size_t)t * H + k0) * B + b]     = h_0;
        hT[((size_t)t * H + k0 + 1) * B + b] = h_1;
        if (h1)
            *(float2*)&h1[((size_t)b * T + t) * H + k0] = make_float2(h_0, h_1);
        if (last && t == myseq)
            *(float2*)&last[(size_t)b * H + k0] = make_float2(h_0, h_1);

        // ---- grid barrier (sense-reversal) ----
        __threadfence();
        __syncthreads();
        if (tid == 0) {
            unsigned gen = *(volatile unsigned*)&g_bar_gen;
            unsigned a = atomicAdd(&g_bar_count, 1u);
            if (a == (unsigned)(gridDim.x - 1)) {
                g_bar_count = 0;
                __threadfence();
                atomicAdd(&g_bar_gen, 1u);
            } else {
                while (*(volatile unsigned*)&g_bar_gen == gen) {}
            }
        }
        __syncthreads();
    }
}

// ---------------- launch ----------------
extern "C" void kernel_launch(void* const* d_in, const int* in_sizes, int n_in,
                              void* d_out, int out_size) {
    const int*   feat  = (const int*)d_in[0];
    const float* emb   = (const float*)d_in[1];
    const float* w_ih0 = (const float*)d_in[2];
    const float* w_hh0 = (const float*)d_in[3];
    const float* b_ih0 = (const float*)d_in[4];
    const float* b_hh0 = (const float*)d_in[5];
    const float* w_ih1 = (const float*)d_in[6];
    const float* w_hh1 = (const float*)d_in[7];
    const float* b_ih1 = (const float*)d_in[8];
    const float* b_hh1 = (const float*)d_in[9];
    const float* fc_w  = (const float*)d_in[10];
    const float* fc_b  = (const float*)d_in[11];
    float* out = (float*)d_out;

    float *x0, *xg, *h1, *hT, *last;
    int* sl;
    cudaGetSymbolAddress((void**)&x0,   g_x0);
    cudaGetSymbolAddress((void**)&xg,   g_xg);
    cudaGetSymbolAddress((void**)&h1,   g_h1);
    cudaGetSymbolAddress((void**)&hT,   g_hT);
    cudaGetSymbolAddress((void**)&last, g_last);
    cudaGetSymbolAddress((void**)&sl,   g_seqlen);

    static int smem_set = 0;
    const int REC_SMEM = (32768 + 2 * 8192) * 4;   // 192 KB
    if (!smem_set) {
        cudaFuncSetAttribute(lstm_rec, cudaFuncAttributeMaxDynamicSharedMemorySize,
                             REC_SMEM);
        smem_set = 1;
    }

    seqlen_kernel<<<B, 256>>>(feat, sl);
    embed_kernel<<<B * T, E / 4>>>(feat, emb, x0);

    // Layer-0 input projection: xg = x0 @ w_ih0^T + (b_ih0 + b_hh0)
    gemm_tn<<<dim3(G4 / 64, (B * T) / 64, 1), 256>>>(
        x0, E, w_ih0, E, b_ih0, b_hh0, xg, G4, E);

    // Layer-0 recurrence (persistent)
    lstm_rec<<<GRID_REC, 256, REC_SMEM>>>(xg, w_hh0, hT, h1, sl, nullptr);

    // Layer-1 input projection: xg = h1 @ w_ih1^T + (b_ih1 + b_hh1)
    gemm_tn<<<dim3(G4 / 64, (B * T) / 64, 1), 256>>>(
        h1, H, w_ih1, H, b_ih1, b_hh1, xg, G4, H);

    // Layer-1 recurrence (persistent, gathers h at seq_lens)
    lstm_rec<<<GRID_REC, 256, REC_SMEM>>>(xg, w_hh1, hT, nullptr, sl, last);

    // FC head: out = last @ fc_w^T + fc_b
    gemm_tn<<<dim3(NC / 64, 1, 1), 256>>>(
        last, H, fc_w, H, fc_b, nullptr, out, NC, H);
}